// round 11
// baseline (speedup 1.0000x reference)
#include <cuda_runtime.h>

// ---------------------------------------------------------------------------
// CML2DWithStats, fused temporal-blocking kernel (Round 9, third submit —
// prior two attempts hit broker/container failures; never executed).
// Base geometry = Round 6 (197us best): one CTA per (batch*chan, 32-row
// band); 66-logical-row x 264-col double-buffered smem window (139 KB);
// shrinking cone [s+1, 62-s]; 512 threads, 4-column x-groups.
//
// Changes vs Round 6 (critical-path attack; R7/R8 falsified instr-count and
// occupancy as levers):
//  1. Balanced halo: active halo rows [s+1,15] / [48,62-s] split across
//     ty 0-3 / 4-7 in contiguous chunks of len=ceil((15-s)/4) (4 -> 1),
//     instead of static quads. Per-step critical path: 4+len rows instead
//     of 8 (sum 92 vs 120 row-units).
//  2. Register-resident interior rows: a thread's interior window rows are
//     its own previous outputs; keep mapped float4s in Rm[4], rebuild
//     windows with shuffles + edge-lane scalar LDS. Interior LDS.128 per
//     quad per step: 6 -> 2. Drive re-read via __ldg (L1-resident).
// ---------------------------------------------------------------------------

#define SSTR  264                      // smem row stride (floats)
#define LROWS 66                       // logical rows -1..64 (physical 0..65)
#define NBUF  (LROWS * SSTR)           // 17424 floats per buffer
#define PL    8388608L                 // elements per output plane

// Window m[x0-1 .. x0+4] from an LDS.128 of the row.
__device__ __forceinline__ void load6(const float* __restrict__ p, int lane, float m[6]) {
    float4 v = *reinterpret_cast<const float4*>(p);
    float left  = __shfl_up_sync(0xffffffffu, v.w, 1);
    float right = __shfl_down_sync(0xffffffffu, v.x, 1);
    if (lane == 0)  left  = p[-1];
    if (lane == 31) right = p[4];
    m[0] = left; m[1] = v.x; m[2] = v.y; m[3] = v.z; m[4] = v.w; m[5] = right;
}

// Window from a register-resident float4 (own previous output); edge lanes
// fall back to prev-step smem (p points into src at this row; that row was
// written last step, so values match the registers).
__device__ __forceinline__ void win6(float4 v, const float* __restrict__ p,
                                     int lane, float m[6]) {
    float left  = __shfl_up_sync(0xffffffffu, v.w, 1);
    float right = __shfl_down_sync(0xffffffffu, v.x, 1);
    if (lane == 0)  left  = p[-1];
    if (lane == 31) right = p[4];
    m[0] = left; m[1] = v.x; m[2] = v.y; m[3] = v.z; m[4] = v.w; m[5] = right;
}

// Folded update: g = sum(W .* mapped_nbr) + 0.15*drive, clamped.
__device__ __forceinline__ void taps(const float* __restrict__ W,
                                     const float A[6], const float B[6],
                                     const float C[6], const float4 d4,
                                     float g[4]) {
    const float dd[4] = {d4.x, d4.y, d4.z, d4.w};
    #pragma unroll
    for (int j = 0; j < 4; ++j) {
        float t =      W[0] * A[j];
        t = fmaf(W[1], A[j + 1], t);
        t = fmaf(W[2], A[j + 2], t);
        t = fmaf(W[3], B[j],     t);
        t = fmaf(W[4], B[j + 1], t);
        t = fmaf(W[5], B[j + 2], t);
        t = fmaf(W[6], C[j],     t);
        t = fmaf(W[7], C[j + 1], t);
        t = fmaf(W[8], C[j + 2], t);
        t = fmaf(0.15f, dd[j],   t);
        g[j] = fminf(fmaxf(t, 1e-4f), 1.0f - 1e-4f);
    }
}

__device__ __forceinline__ float4 lmap(const float g[4]) {
    float4 m;
    m.x = (3.9f * g[0]) * (1.0f - g[0]);
    m.y = (3.9f * g[1]) * (1.0f - g[1]);
    m.z = (3.9f * g[2]) * (1.0f - g[2]);
    m.w = (3.9f * g[3]) * (1.0f - g[3]);
    return m;
}

// Balanced halo: at step s this warp (ty) owns a contiguous chunk of the
// active halo rows. Chunk bounds are warp-uniform. Per-row image-y check
// predicates the write; window reads stay inside rows the previous step
// produced ([lo-1, hi+1]).
__device__ __forceinline__ void halo_bal(
    const float* __restrict__ srcb, float* __restrict__ dstb,
    int s, int ty, int lane, int x0, int y0,
    const float* __restrict__ dpl, const float* __restrict__ W)
{
    const int lo  = s + 1, hi = 62 - s;
    const int n   = 15 - s;                 // rows per half
    const int len = (n + 3) >> 2;           // ceil(n/4), 4..1
    const int t   = (ty < 4) ? ty : (ty - 4);
    const int start = (ty < 4) ? (lo + t * len) : (48 + t * len);
    const int lim   = (ty < 4) ? 15 : hi;
    const int end   = (start + len - 1 < lim) ? (start + len - 1) : lim;
    if (start > end) return;

    const float* pA = srcb + (start - 1) * SSTR + 4 + x0;
    float A[6], B[6], C[6];
    load6(pA,        lane, A);
    load6(pA + SSTR, lane, B);
    #pragma unroll
    for (int i = 0; i < 4; ++i) {
        const int r = start + i;
        if (r <= end) {                      // warp-uniform, monotone
            load6(pA + (i + 2) * SSTR, lane, C);
            const int y = y0 - 16 + r;
            if (y >= 0 && y <= 255) {
                const float4 d4 = __ldg(reinterpret_cast<const float4*>(dpl + y * 256 + x0));
                float g[4];
                taps(W, A, B, C, d4, g);
                *reinterpret_cast<float4*>(dstb + r * SSTR + 4 + x0) = lmap(g);
            }
            #pragma unroll
            for (int q = 0; q < 6; ++q) { A[q] = B[q]; B[q] = C[q]; }
        }
    }
}

// Interior quad [R0, R0+3] subset of [16,47]: always in-cone, unconditional.
// Rows R0..R0+3 windows come from register-resident Rm (own prev outputs);
// rows R0-1 and R0+4 via load6.
template<bool LAST>
__device__ __forceinline__ void int_block(
    const float* __restrict__ srcb, float* __restrict__ dstb,
    int R0, int lane, int x0, int y0,
    const float* __restrict__ dpl, const float* __restrict__ W,
    float4 (&Rm)[4], float (&sum)[4][4], float (&sq)[4][4],
    float* __restrict__ outBase)
{
    const float* pA = srcb + (R0 - 1) * SSTR + 4 + x0;
    float A[6], B[6], C[6];
    load6(pA, lane, A);
    win6(Rm[0], pA + SSTR, lane, B);
    #pragma unroll
    for (int i = 0; i < 4; ++i) {
        if (i < 3) win6(Rm[i + 1], pA + (i + 2) * SSTR, lane, C);
        else       load6(pA + 5 * SSTR, lane, C);
        const int y = y0 + (R0 - 16) + i;
        const float4 d4 = __ldg(reinterpret_cast<const float4*>(dpl + y * 256 + x0));
        float g[4];
        taps(W, A, B, C, d4, g);
        #pragma unroll
        for (int j = 0; j < 4; ++j) {
            sum[i][j] += g[j];
            sq[i][j]   = fmaf(g[j], g[j], sq[i][j]);
        }
        if (!LAST) {
            const float4 mv = lmap(g);
            Rm[i] = mv;
            *reinterpret_cast<float4*>(dstb + (R0 + i) * SSTR + 4 + x0) = mv;
        } else {
            const long o = (long)y * 256 + x0;
            *reinterpret_cast<float4*>(outBase + o) =
                make_float4(g[0], g[1], g[2], g[3]);
            const float4 dl = make_float4(g[0] - d4.x, g[1] - d4.y,
                                          g[2] - d4.z, g[3] - d4.w);
            *reinterpret_cast<float4*>(outBase + 3L * PL + o) = dl;
            *reinterpret_cast<float4*>(outBase + 4L * PL + o) = dl;
        }
        #pragma unroll
        for (int q = 0; q < 6; ++q) { A[q] = B[q]; B[q] = C[q]; }
    }
}

__global__ void __launch_bounds__(512, 1)
cml_fused_kernel(const float* __restrict__ drive,
                 const float* __restrict__ Kl,
                 float* __restrict__ out)
{
    extern __shared__ float smem[];
    float* b0 = smem + SSTR;           // logical row 0 of buffer 0
    float* b1 = smem + NBUF + SSTR;    // logical row 0 of buffer 1

    const int tile = blockIdx.x;       // (b*8 + c)*8 + band
    const int band = tile & 7;
    const int bc   = tile >> 3;
    const int ch   = bc & 7;
    const int y0   = band * 32;
    const float* dpl     = drive + (long)bc * 65536L;
    float*       outBase = out   + (long)bc * 65536L;

    const int tid  = threadIdx.x;
    const int tx   = tid & 63;         // x group (4 columns)
    const int ty   = tid >> 6;         // 0..7, warp-uniform
    const int lane = tid & 31;
    const int x0   = tx << 2;

    // Interior quad ownership (halo is distributed dynamically per step).
    const int Ri = 16 + 4 * ty;        // [16,47] covered by ty 0..7

    // Folded conv weights: W = 0.255*K, +0.595 at center.
    float W[9];
    #pragma unroll
    for (int i = 0; i < 9; ++i) W[i] = 0.255f * __ldg(&Kl[ch * 9 + i]);
    W[4] += 0.595f;

    // Zero both buffers (guards + out-of-image rows = conv zero padding).
    for (int i = tid; i < 2 * NBUF; i += 512) smem[i] = 0.0f;
    __syncthreads();

    // Init buffer 0 with mapped(drive) on logical rows 1..62 (valid y only).
    for (int idx = tid; idx < 62 * 64; idx += 512) {
        const int r  = 1 + (idx >> 6);
        const int xg = (idx & 63) << 2;
        const int y  = y0 - 16 + r;
        if (y >= 0 && y < 256) {
            const float4 d = *reinterpret_cast<const float4*>(dpl + y * 256 + xg);
            float4 m;
            m.x = (3.9f * d.x) * (1.0f - d.x);
            m.y = (3.9f * d.y) * (1.0f - d.y);
            m.z = (3.9f * d.z) * (1.0f - d.z);
            m.w = (3.9f * d.w) * (1.0f - d.w);
            *reinterpret_cast<float4*>(b0 + r * SSTR + 4 + xg) = m;
        }
    }
    __syncthreads();

    // Register-resident interior rows: own mapped(drive) values.
    float4 Rm[4];
    #pragma unroll
    for (int i = 0; i < 4; ++i)
        Rm[i] = *reinterpret_cast<const float4*>(b0 + (Ri + i) * SSTR + 4 + x0);

    float sum[4][4], sq[4][4];
    #pragma unroll
    for (int i = 0; i < 4; ++i)
        #pragma unroll
        for (int j = 0; j < 4; ++j) { sum[i][j] = 0.0f; sq[i][j] = 0.0f; }

    const float* src = b0;
    float*       dst = b1;
    for (int s = 1; s <= 14; ++s) {
        halo_bal(src, dst, s, ty, lane, x0, y0, dpl, W);
        int_block<false>(src, dst, Ri, lane, x0, y0, dpl, W, Rm, sum, sq, outBase);
        const float* t = src; src = dst; dst = const_cast<float*>(t);
        __syncthreads();
    }
    // Step 15: cone == interior.
    int_block<true>(src, dst, Ri, lane, x0, y0, dpl, W, Rm, sum, sq, outBase);

    // mean / var from register accumulators.
    const float inv15 = 1.0f / 15.0f;
    #pragma unroll
    for (int i = 0; i < 4; ++i) {
        const int y = y0 + (Ri - 16) + i;
        const long o = (long)y * 256 + x0;
        float4 mn, vr;
        mn.x = sum[i][0] * inv15;
        mn.y = sum[i][1] * inv15;
        mn.z = sum[i][2] * inv15;
        mn.w = sum[i][3] * inv15;
        vr.x = fmaf(-mn.x, mn.x, sq[i][0] * inv15);
        vr.y = fmaf(-mn.y, mn.y, sq[i][1] * inv15);
        vr.z = fmaf(-mn.z, mn.z, sq[i][2] * inv15);
        vr.w = fmaf(-mn.w, mn.w, sq[i][3] * inv15);
        *reinterpret_cast<float4*>(outBase + 1L * PL + o) = mn;
        *reinterpret_cast<float4*>(outBase + 2L * PL + o) = vr;
    }
}

extern "C" void kernel_launch(void* const* d_in, const int* in_sizes, int n_in,
                              void* d_out, int out_size)
{
    const float* drive = (const float*)d_in[0];
    const float* Kl    = (const float*)d_in[1];
    if (n_in >= 2 && in_sizes[0] == 72) {         // defensive input-order check
        const float* t = drive; drive = Kl; Kl = t;
    }
    float* out = (float*)d_out;
    (void)out_size;

    const size_t shmem = 2 * NBUF * sizeof(float);   // 139392 bytes
    cudaFuncSetAttribute(cml_fused_kernel,
                         cudaFuncAttributeMaxDynamicSharedMemorySize, (int)shmem);
    cml_fused_kernel<<<1024, 512, shmem>>>(drive, Kl, out);
}

// round 12
// speedup vs baseline: 1.0764x; 1.0764x over previous
#include <cuda_runtime.h>

// ---------------------------------------------------------------------------
// CML2DWithStats, fused temporal-blocking kernel (Round 12).
// EXACT Round-6 base (197us best: one CTA per (batch*chan, 32-row band);
// 66-logical-row x 264-col double-buffered smem window; cone [s+1, 62-s];
// 512 threads, 4-col x-groups; static interior quad with register-resident
// drive) with ONE isolated change:
//
//   Balanced halo (bisect of Round-9's bundled pair): the active halo rows
//   [s+1,15] / [48,62-s] are split across ty 0-3 / ty 4-7 in contiguous
//   chunks of len=ceil((15-s)/4) (4 -> 1 as s grows), replacing the static
//   halo quads. Slowest-warp critical path: 92 vs 110 row-units.
//
// Round-9's other half (register-resident interior windows) is NOT included:
// it pushed regs to the 128 cap and regressed (227us).
// ---------------------------------------------------------------------------

#define SSTR  264                      // smem row stride (floats)
#define LROWS 66                       // logical rows -1..64 (physical 0..65)
#define NBUF  (LROWS * SSTR)           // 17424 floats per buffer
#define PL    8388608L                 // elements per output plane

// mapped[x0-1 .. x0+4] for one row: one LDS.128 + 2 shuffles; edge lanes
// read the in-row halo columns (4-col zero pads exist both sides).
__device__ __forceinline__ void load6(const float* __restrict__ p, int lane, float m[6]) {
    float4 v = *reinterpret_cast<const float4*>(p);
    float left  = __shfl_up_sync(0xffffffffu, v.w, 1);
    float right = __shfl_down_sync(0xffffffffu, v.x, 1);
    if (lane == 0)  left  = p[-1];
    if (lane == 31) right = p[4];
    m[0] = left; m[1] = v.x; m[2] = v.y; m[3] = v.z; m[4] = v.w; m[5] = right;
}

// Folded update: g = sum(W .* mapped_nbr) + 0.15*drive, clamped.
__device__ __forceinline__ void taps(const float* __restrict__ W,
                                     const float A[6], const float B[6],
                                     const float C[6], const float dd[4],
                                     float g[4]) {
    #pragma unroll
    for (int j = 0; j < 4; ++j) {
        float t =      W[0] * A[j];
        t = fmaf(W[1], A[j + 1], t);
        t = fmaf(W[2], A[j + 2], t);
        t = fmaf(W[3], B[j],     t);
        t = fmaf(W[4], B[j + 1], t);
        t = fmaf(W[5], B[j + 2], t);
        t = fmaf(W[6], C[j],     t);
        t = fmaf(W[7], C[j + 1], t);
        t = fmaf(W[8], C[j + 2], t);
        t = fmaf(0.15f, dd[j],   t);
        g[j] = fminf(fmaxf(t, 1e-4f), 1.0f - 1e-4f);
    }
}

// Balanced halo: at step s this warp (ty) owns a contiguous chunk of the
// active halo rows. Chunk bounds warp-uniform; rolling-load predicate is
// warp-uniform and monotone over the unrolled i. Window reads stay inside
// [lo-1, hi+1] = rows the previous step produced.
__device__ __forceinline__ void halo_bal(
    const float* __restrict__ srcb, float* __restrict__ dstb,
    int s, int ty, int lane, int x0, int y0,
    const float* __restrict__ dpl, const float* __restrict__ W)
{
    const int lo  = s + 1, hi = 62 - s;
    const int n   = 15 - s;                 // rows per half
    const int len = (n + 3) >> 2;           // ceil(n/4), 4..1
    const int t   = (ty < 4) ? ty : (ty - 4);
    const int start = (ty < 4) ? (lo + t * len) : (48 + t * len);
    const int lim   = (ty < 4) ? 15 : hi;
    const int end   = (start + len - 1 < lim) ? (start + len - 1) : lim;
    if (start > end) return;

    const float* pA = srcb + (start - 1) * SSTR + 4 + x0;
    float A[6], B[6], C[6];
    load6(pA,        lane, A);
    load6(pA + SSTR, lane, B);
    #pragma unroll
    for (int i = 0; i < 4; ++i) {
        const int r = start + i;
        if (r <= end) {                      // warp-uniform, monotone
            load6(pA + (i + 2) * SSTR, lane, C);
            const int y = y0 - 16 + r;
            if (y >= 0 && y <= 255) {
                const float4 d4 = __ldg(reinterpret_cast<const float4*>(dpl + y * 256 + x0));
                const float dd[4] = {d4.x, d4.y, d4.z, d4.w};
                float g[4];
                taps(W, A, B, C, dd, g);
                float4 mv;
                mv.x = (3.9f * g[0]) * (1.0f - g[0]);
                mv.y = (3.9f * g[1]) * (1.0f - g[1]);
                mv.z = (3.9f * g[2]) * (1.0f - g[2]);
                mv.w = (3.9f * g[3]) * (1.0f - g[3]);
                *reinterpret_cast<float4*>(dstb + r * SSTR + 4 + x0) = mv;
            }
            #pragma unroll
            for (int q = 0; q < 6; ++q) { A[q] = B[q]; B[q] = C[q]; }
        }
    }
}

// Interior quad [R0, R0+3] subset of [16,47]: always in-cone, unconditional.
// Identical to Round 6: load6 windows, register-resident drive (ddreg).
template<bool LAST>
__device__ __forceinline__ void int_block(
    const float* __restrict__ srcb, float* __restrict__ dstb,
    int R0, int lane, int x0, int y0,
    const float (&ddreg)[4][4], const float* __restrict__ W,
    float (&sum)[4][4], float (&sq)[4][4], float* __restrict__ outBase)
{
    const float* pA = srcb + (R0 - 1) * SSTR + 4 + x0;
    float A[6], B[6], C[6];
    load6(pA,        lane, A);
    load6(pA + SSTR, lane, B);
    #pragma unroll
    for (int i = 0; i < 4; ++i) {
        load6(pA + (i + 2) * SSTR, lane, C);
        float g[4];
        taps(W, A, B, C, ddreg[i], g);
        #pragma unroll
        for (int j = 0; j < 4; ++j) {
            sum[i][j] += g[j];
            sq[i][j]   = fmaf(g[j], g[j], sq[i][j]);
        }
        if (!LAST) {
            float4 mv;
            mv.x = (3.9f * g[0]) * (1.0f - g[0]);
            mv.y = (3.9f * g[1]) * (1.0f - g[1]);
            mv.z = (3.9f * g[2]) * (1.0f - g[2]);
            mv.w = (3.9f * g[3]) * (1.0f - g[3]);
            *reinterpret_cast<float4*>(dstb + (R0 + i) * SSTR + 4 + x0) = mv;
        } else {
            const int y = y0 + (R0 - 16) + i;
            const long o = (long)y * 256 + x0;
            *reinterpret_cast<float4*>(outBase + o) =
                make_float4(g[0], g[1], g[2], g[3]);
            const float4 dl = make_float4(g[0] - ddreg[i][0], g[1] - ddreg[i][1],
                                          g[2] - ddreg[i][2], g[3] - ddreg[i][3]);
            *reinterpret_cast<float4*>(outBase + 3L * PL + o) = dl;
            *reinterpret_cast<float4*>(outBase + 4L * PL + o) = dl;
        }
        #pragma unroll
        for (int q = 0; q < 6; ++q) { A[q] = B[q]; B[q] = C[q]; }
    }
}

__global__ void __launch_bounds__(512, 1)
cml_fused_kernel(const float* __restrict__ drive,
                 const float* __restrict__ Kl,
                 float* __restrict__ out)
{
    extern __shared__ float smem[];
    float* b0 = smem + SSTR;           // logical row 0 of buffer 0
    float* b1 = smem + NBUF + SSTR;    // logical row 0 of buffer 1

    const int tile = blockIdx.x;       // (b*8 + c)*8 + band
    const int band = tile & 7;
    const int bc   = tile >> 3;
    const int ch   = bc & 7;
    const int y0   = band * 32;
    const float* dpl     = drive + (long)bc * 65536L;
    float*       outBase = out   + (long)bc * 65536L;

    const int tid  = threadIdx.x;
    const int tx   = tid & 63;         // x group (4 columns)
    const int ty   = tid >> 6;         // 0..7, warp-uniform
    const int lane = tid & 31;
    const int x0   = tx << 2;

    // Static interior quad; halo distributed dynamically per step.
    const int Ri = 16 + 4 * ty;        // [16,47] covered by ty 0..7

    // Folded conv weights: W = 0.255*K, +0.595 at center.
    float W[9];
    #pragma unroll
    for (int i = 0; i < 9; ++i) W[i] = 0.255f * __ldg(&Kl[ch * 9 + i]);
    W[4] += 0.595f;

    // Interior drive values live in registers for all 15 steps (as in R6).
    float ddreg[4][4];
    #pragma unroll
    for (int i = 0; i < 4; ++i) {
        const int y = y0 + (Ri - 16) + i;
        const float4 d4 = *reinterpret_cast<const float4*>(dpl + y * 256 + x0);
        ddreg[i][0] = d4.x; ddreg[i][1] = d4.y;
        ddreg[i][2] = d4.z; ddreg[i][3] = d4.w;
    }

    // Zero both buffers (guards + out-of-image rows = conv zero padding).
    for (int i = tid; i < 2 * NBUF; i += 512) smem[i] = 0.0f;
    __syncthreads();

    // Init buffer 0 with mapped(drive) on logical rows 1..62 (valid y only).
    for (int idx = tid; idx < 62 * 64; idx += 512) {
        const int r  = 1 + (idx >> 6);
        const int xg = (idx & 63) << 2;
        const int y  = y0 - 16 + r;
        if (y >= 0 && y < 256) {
            const float4 d = *reinterpret_cast<const float4*>(dpl + y * 256 + xg);
            float4 m;
            m.x = (3.9f * d.x) * (1.0f - d.x);
            m.y = (3.9f * d.y) * (1.0f - d.y);
            m.z = (3.9f * d.z) * (1.0f - d.z);
            m.w = (3.9f * d.w) * (1.0f - d.w);
            *reinterpret_cast<float4*>(b0 + r * SSTR + 4 + xg) = m;
        }
    }
    __syncthreads();

    float sum[4][4], sq[4][4];
    #pragma unroll
    for (int i = 0; i < 4; ++i)
        #pragma unroll
        for (int j = 0; j < 4; ++j) { sum[i][j] = 0.0f; sq[i][j] = 0.0f; }

    const float* src = b0;
    float*       dst = b1;
    for (int s = 1; s <= 14; ++s) {
        halo_bal(src, dst, s, ty, lane, x0, y0, dpl, W);
        int_block<false>(src, dst, Ri, lane, x0, y0, ddreg, W, sum, sq, outBase);
        const float* t = src; src = dst; dst = const_cast<float*>(t);
        __syncthreads();
    }
    // Step 15: cone == interior.
    int_block<true>(src, dst, Ri, lane, x0, y0, ddreg, W, sum, sq, outBase);

    // mean / var from register accumulators.
    const float inv15 = 1.0f / 15.0f;
    #pragma unroll
    for (int i = 0; i < 4; ++i) {
        const int y = y0 + (Ri - 16) + i;
        const long o = (long)y * 256 + x0;
        float4 mn, vr;
        mn.x = sum[i][0] * inv15;
        mn.y = sum[i][1] * inv15;
        mn.z = sum[i][2] * inv15;
        mn.w = sum[i][3] * inv15;
        vr.x = fmaf(-mn.x, mn.x, sq[i][0] * inv15);
        vr.y = fmaf(-mn.y, mn.y, sq[i][1] * inv15);
        vr.z = fmaf(-mn.z, mn.z, sq[i][2] * inv15);
        vr.w = fmaf(-mn.w, mn.w, sq[i][3] * inv15);
        *reinterpret_cast<float4*>(outBase + 1L * PL + o) = mn;
        *reinterpret_cast<float4*>(outBase + 2L * PL + o) = vr;
    }
}

extern "C" void kernel_launch(void* const* d_in, const int* in_sizes, int n_in,
                              void* d_out, int out_size)
{
    const float* drive = (const float*)d_in[0];
    const float* Kl    = (const float*)d_in[1];
    if (n_in >= 2 && in_sizes[0] == 72) {         // defensive input-order check
        const float* t = drive; drive = Kl; Kl = t;
    }
    float* out = (float*)d_out;
    (void)out_size;

    const size_t shmem = 2 * NBUF * sizeof(float);   // 139392 bytes
    cudaFuncSetAttribute(cml_fused_kernel,
                         cudaFuncAttributeMaxDynamicSharedMemorySize, (int)shmem);
    cml_fused_kernel<<<1024, 512, shmem>>>(drive, Kl, out);
}